// round 9
// baseline (speedup 1.0000x reference)
#include <cuda_runtime.h>

#define H_ 4
#define D_ 64
#define L_ 7
#define VOCAB_ 6
#define NOUT_ 11
#define BATCH_ 32768
#define EPS_ 1e-5f

using u64 = unsigned long long;

// ---- packed f32x2 helpers (sm_100+) ----
__device__ __forceinline__ u64 pk2(float x, float y) {
    u64 r; asm("mov.b64 %0, {%1, %2};" : "=l"(r) : "f"(x), "f"(y)); return r;
}
__device__ __forceinline__ u64 bc2(float x) {
    u64 r; asm("mov.b64 %0, {%1, %1};" : "=l"(r) : "f"(x)); return r;
}
__device__ __forceinline__ void fma2(u64& a, u64 x, u64 w) {
    asm("fma.rn.f32x2 %0, %1, %2, %0;" : "+l"(a) : "l"(x), "l"(w));
}
__device__ __forceinline__ u64 add2(u64 a, u64 b) {
    u64 r; asm("add.rn.f32x2 %0, %1, %2;" : "=l"(r) : "l"(a), "l"(b)); return r;
}
__device__ __forceinline__ float2 up2(u64 v) {
    float2 r; asm("mov.b64 {%0, %1}, %2;" : "=f"(r.x), "=f"(r.y) : "l"(v)); return r;
}

// ---------------- scratch (no allocations allowed) ----------------
__device__ float g_E[H_ * L_ * VOCAB_ * L_ * VOCAB_]; // [h][k][tk][q][tq]
__device__ float g_VW[H_ * L_ * VOCAB_ * D_];         // [(h*7+k)*6+tk][64]
__device__ float g_Wf[D_ * NOUT_];
__device__ float g_bf[NOUT_];
__device__ float g_C1t[128 * 64];   // [c][ (k+4c)&63 ]  transposed+rotated C1
__device__ float g_C2t[64 * 128];   // [c][ (k+4c)&127 ] transposed+rotated C2

// ---------------- single merged prep kernel ----------------
__global__ void k_prep(const float* __restrict__ emb, const float* __restrict__ pos,
                       const float* __restrict__ in_w, const float* __restrict__ in_b,
                       const float* __restrict__ e_wq, const float* __restrict__ e_wk,
                       const float* __restrict__ e_wv, const float* __restrict__ e_wo,
                       const float* __restrict__ d_wv, const float* __restrict__ d_wo,
                       const float* __restrict__ d_bo,
                       const float* __restrict__ fc_w, const float* __restrict__ fc_b,
                       const float* __restrict__ c1w, const float* __restrict__ c2w) {
    extern __shared__ float dyn[];
    int tid = threadIdx.x;
    int cta = blockIdx.x;

    if (cta < 8) {
        float* sT = dyn;          // 2688
        float* sA = dyn + 2688;   // 2688
        float* sB = dyn + 5376;   // 2688
        for (int i = tid; i < 42 * 64; i += 1024) {
            int lv = i >> 6, e = i & 63;
            int l = lv / 6, v = lv % 6;
            float acc = in_b[e];
            #pragma unroll 8
            for (int d = 0; d < 64; d++) acc = fmaf(emb[v * 64 + d], in_w[d * 64 + e], acc);
            acc = fmaf(pos[l], in_w[64 * 64 + e], acc);
            sT[i] = acc;
        }
        __syncthreads();
        int h = cta & 3;
        if (cta < 4) {
            for (int i = tid; i < 2 * 2688; i += 1024) {
                int which = i / 2688, r = i % 2688;
                int lv = r >> 6, e = r & 63;
                const float* w = which ? e_wk : e_wq;
                float acc = 0.f;
                #pragma unroll 8
                for (int d = 0; d < 64; d++) acc = fmaf(sT[lv * 64 + d], w[(h * 64 + d) * 64 + e], acc);
                (which ? sB : sA)[r] = acc;
            }
            __syncthreads();
            for (int i = tid; i < 1764; i += 1024) {
                int r = i;
                int tq = r % 6; r /= 6;
                int q  = r % 7; r /= 7;
                int tk = r % 6; r /= 6;
                int k  = r;
                const float* Q = sA + (q * 6 + tq) * 64;
                const float* K = sB + (k * 6 + tk) * 64;
                float s = 0.f;
                #pragma unroll 8
                for (int d = 0; d < 64; d++) s = fmaf(Q[d], K[d], s);
                g_E[h * 1764 + i] = __expf(s * 0.125f);
            }
        } else {
            for (int i = tid; i < 2688; i += 1024) {
                int lv = i >> 6, e = i & 63;
                float acc = 0.f;
                #pragma unroll 8
                for (int d = 0; d < 64; d++) acc = fmaf(sT[lv * 64 + d], e_wv[(h * 64 + d) * 64 + e], acc);
                sA[i] = acc;
            }
            __syncthreads();
            for (int i = tid; i < 2688; i += 1024) {
                int kv = i >> 6, e = i & 63;
                float acc = 0.f;
                #pragma unroll 8
                for (int d = 0; d < 64; d++) acc = fmaf(sA[kv * 64 + d], e_wo[(h * 64 + d) * 64 + e], acc);
                g_VW[(h * 42 + kv) * 64 + e] = acc;
            }
        }
    } else {
        float* sWd = dyn;  // 4096
        for (int i = tid; i < 4096; i += 1024) {
            int r = i >> 6, j = i & 63;
            float acc = 0.f;
            for (int hh = 0; hh < 4; hh++)
                #pragma unroll 8
                for (int d = 0; d < 64; d++)
                    acc = fmaf(d_wv[(hh * 64 + r) * 64 + d], d_wo[(hh * 64 + d) * 64 + j], acc);
            sWd[i] = acc;
        }
        __syncthreads();
        for (int i = tid; i < 64 * NOUT_; i += 1024) {
            int r = i / NOUT_, n = i % NOUT_;
            float acc = 0.f;
            #pragma unroll 8
            for (int j = 0; j < 64; j++) acc = fmaf(sWd[r * 64 + j], fc_w[j * NOUT_ + n], acc);
            g_Wf[i] = acc;
        }
        if (tid < NOUT_) {
            float b = fc_b[tid];
            #pragma unroll 8
            for (int j = 0; j < 64; j++) b = fmaf(d_bo[j], fc_w[j * NOUT_ + tid], b);
            g_bf[tid] = b;
        }
        // transposed + bank-rotated FFN weights
        for (int i = tid; i < 128 * 64; i += 1024) {
            int c = i >> 6, k = i & 63;
            g_C1t[c * 64 + ((k + 4 * c) & 63)] = c1w[k * 128 + c];
        }
        for (int i = tid; i < 64 * 128; i += 1024) {
            int c = i >> 7, k = i & 127;
            g_C2t[c * 128 + ((k + 4 * c) & 127)] = c2w[k * 64 + c];
        }
    }
}

// ---------------- main fused kernel ----------------
// 12 warps/CTA, 1 CTA/SM. SMEM (floats):
//   sE 7056 | sVW 10752 | sC1t 8192 | sC2t 8192 | sWf 704 | sBf 16  (=34912)
//   per-warp: wco 224 | xn 448 | h1 896  (=1568)
#define NWARP 12
#define NTHR  (NWARP * 32)
#define SMEM_FLOATS (34912 + NWARP * 1568)

__global__ __launch_bounds__(NTHR, 1)
void k_main(const int* __restrict__ tokens,
            const float* __restrict__ e_bo,
            const float* __restrict__ g1, const float* __restrict__ b1,
            const float* __restrict__ c1b, const float* __restrict__ c2b,
            const float* __restrict__ g2, const float* __restrict__ b2,
            float* __restrict__ out, int totalWarps) {
    extern __shared__ float sm[];
    float* sE   = sm;                 // 7056
    float* sVW  = sE + 7056;          // 10752
    float* sC1  = sVW + 10752;        // 8192 (transposed+rotated)
    float* sC2  = sC1 + 8192;         // 8192 (transposed+rotated)
    float* sWf  = sC2 + 8192;         // 704
    float* sBf  = sWf + 704;          // 16
    float* sWco = sBf + 16;           // NWARP*224
    float* sXn  = sWco + NWARP * 224; // NWARP*448
    float* sH1  = sXn + NWARP * 448;  // NWARP*896

    int tid = threadIdx.x;

    for (int i = tid; i < 7056 / 4;  i += NTHR) ((float4*)sE)[i]  = ((const float4*)g_E)[i];
    for (int i = tid; i < 10752 / 4; i += NTHR) ((float4*)sVW)[i] = ((const float4*)g_VW)[i];
    for (int i = tid; i < 8192 / 4;  i += NTHR) ((float4*)sC1)[i] = ((const float4*)g_C1t)[i];
    for (int i = tid; i < 8192 / 4;  i += NTHR) ((float4*)sC2)[i] = ((const float4*)g_C2t)[i];
    for (int i = tid; i < 704 / 4;   i += NTHR) ((float4*)sWf)[i] = ((const float4*)g_Wf)[i];
    if (tid < NOUT_) sBf[tid] = g_bf[tid];
    __syncthreads();

    int lane = tid & 31, wid = tid >> 5;

    // params. attention/LN1 lane owns dims (2l, 2l+1); FFN2/LN2/decoder lane owns dims (l, l+32)
    float2 bo2f = ((const float2*)e_bo)[lane];
    u64    bo2  = pk2(bo2f.x, bo2f.y);
    float2 g1v  = ((const float2*)g1)[lane];
    float2 b1v  = ((const float2*)b1)[lane];
    float  g2a  = g2[lane], g2b = g2[lane + 32];
    float  b2a  = b2[lane], b2b = b2[lane + 32];
    // FFN1 bias for cols {l, l+32, l+64, l+96}, packed as (bias, 0)
    u64 c1bp[4];
    #pragma unroll
    for (int j = 0; j < 4; j++) c1bp[j] = pk2(c1b[lane + 32 * j], 0.f);
    u64 c2bp0 = pk2(c2b[lane], 0.f);
    u64 c2bp1 = pk2(c2b[lane + 32], 0.f);

    float* wcoW = sWco + wid * 224;   // [j][8]
    float* xnW  = sXn + wid * 448;    // 7 rows of 64
    float* h1W  = sH1 + wid * 896;    // 7 rows of 128

    const float* pC1a = sC1 + lane * 64;
    const float* pC2a = sC2 + lane * 128;
    int rot1base = (4 * lane) & 63;
    int rot2base = (4 * lane) & 127;

    int gw = blockIdx.x * NWARP + wid;
    for (int e = gw; e < BATCH_; e += totalWarps) {
        // tokens: one coalesced LDG + shfl broadcast
        int myTok = 0;
        if (lane < 7) myTok = tokens[e * 7 + lane];
        int t[7];
        #pragma unroll
        for (int i = 0; i < 7; i++) t[i] = __shfl_sync(0xffffffffu, myTok, i);

        // softmax-over-q weights, packed wco[j][0..6]
        if (lane < 28) {
            int k = lane % 7;
            const float* eb = sE + (lane * 6 + t[k]) * 42;
            float myw[7];
            float den = 0.f;
            #pragma unroll
            for (int q = 0; q < 7; q++) { float x = eb[q * 6 + t[q]]; myw[q] = x; den += x; }
            float inv = __fdividef(1.f, den);
            float4 wA = make_float4(myw[0] * inv, myw[1] * inv, myw[2] * inv, myw[3] * inv);
            float4 wB = make_float4(myw[4] * inv, myw[5] * inv, myw[6] * inv, 0.f);
            ((float4*)(wcoW + lane * 8))[0] = wA;
            ((float4*)(wcoW + lane * 8))[1] = wB;
        }
        __syncwarp();

        // attention: y[q] = bo + sum_j w[q][j] * VW[j][t_k]  (packed f32x2)
        u64 y[7];
        #pragma unroll
        for (int q = 0; q < 7; q++) y[q] = bo2;
        #pragma unroll
        for (int j = 0; j < 28; j++) {
            int k = j % 7;
            u64 v = ((const u64*)(sVW + (j * 6 + t[k]) * 64))[lane];
            float4 wA = ((const float4*)(wcoW + j * 8))[0];
            float4 wB = ((const float4*)(wcoW + j * 8))[1];
            fma2(y[0], bc2(wA.x), v);
            fma2(y[1], bc2(wA.y), v);
            fma2(y[2], bc2(wA.z), v);
            fma2(y[3], bc2(wA.w), v);
            fma2(y[4], bc2(wB.x), v);
            fma2(y[5], bc2(wB.y), v);
            fma2(y[6], bc2(wB.z), v);
        }

        // LN1 for all 7 q at once, store xn (dims 2l,2l+1) to smem
        {
            float s1[7], ss1[7];
            float2 yf[7];
            #pragma unroll
            for (int q = 0; q < 7; q++) {
                yf[q] = up2(y[q]);
                s1[q]  = yf[q].x + yf[q].y;
                ss1[q] = yf[q].x * yf[q].x + yf[q].y * yf[q].y;
            }
            #pragma unroll
            for (int o = 16; o > 0; o >>= 1) {
                #pragma unroll
                for (int q = 0; q < 7; q++) {
                    s1[q]  += __shfl_xor_sync(0xffffffffu, s1[q], o);
                    ss1[q] += __shfl_xor_sync(0xffffffffu, ss1[q], o);
                }
            }
            #pragma unroll
            for (int q = 0; q < 7; q++) {
                float mean = s1[q] * (1.f / 64.f);
                float var  = ss1[q] * (1.f / 64.f) - mean * mean;
                float rstd = rsqrtf(var + EPS_);
                float2 xn;
                xn.x = (yf[q].x - mean) * rstd * g1v.x + b1v.x;
                xn.y = (yf[q].y - mean) * rstd * g1v.y + b1v.y;
                ((float2*)(xnW + q * 64))[lane] = xn;
            }
        }
        __syncwarp();

        // ---- FFN1: 64 -> 128, k-paired FMA2, transposed rotated weights ----
        // lane owns cols {l, l+32, l+64, l+96}; accE/accO = even/odd k partials
        {
            u64 accE[7][4], accO[7][4];
            #pragma unroll
            for (int i = 0; i < 7; i++)
                #pragma unroll
                for (int j = 0; j < 4; j++) { accE[i][j] = c1bp[j]; accO[i][j] = 0ull; }

            #pragma unroll 2
            for (int d4 = 0; d4 < 16; d4++) {
                int rot = (4 * d4 + rot1base) & 63;
                ulonglong2 w0 = *(const ulonglong2*)(pC1a + rot);
                ulonglong2 w1 = *(const ulonglong2*)(pC1a + 32 * 64 + rot);
                ulonglong2 w2 = *(const ulonglong2*)(pC1a + 64 * 64 + rot);
                ulonglong2 w3 = *(const ulonglong2*)(pC1a + 96 * 64 + rot);
                #pragma unroll
                for (int i = 0; i < 7; i++) {
                    ulonglong2 xp = ((const ulonglong2*)(xnW + i * 64))[d4];
                    fma2(accE[i][0], xp.x, w0.x); fma2(accO[i][0], xp.y, w0.y);
                    fma2(accE[i][1], xp.x, w1.x); fma2(accO[i][1], xp.y, w1.y);
                    fma2(accE[i][2], xp.x, w2.x); fma2(accO[i][2], xp.y, w2.y);
                    fma2(accE[i][3], xp.x, w3.x); fma2(accO[i][3], xp.y, w3.y);
                }
            }
            #pragma unroll
            for (int i = 0; i < 7; i++) {
                #pragma unroll
                for (int j = 0; j < 4; j++) {
                    float2 f = up2(add2(accE[i][j], accO[i][j]));
                    h1W[i * 128 + lane + 32 * j] = fmaxf(f.x + f.y, 0.f);
                }
            }
        }
        __syncwarp();

        // ---- FFN2: 128 -> 64, k-paired FMA2, lane owns cols {l, l+32} ----
        float2 xs = make_float2(0.f, 0.f);
        {
            u64 bE0[7], bO0[7], bE1[7], bO1[7];
            #pragma unroll
            for (int i = 0; i < 7; i++) {
                bE0[i] = c2bp0; bO0[i] = 0ull;
                bE1[i] = c2bp1; bO1[i] = 0ull;
            }
            #pragma unroll 2
            for (int d4 = 0; d4 < 32; d4++) {
                int rot = (4 * d4 + rot2base) & 127;
                ulonglong2 wa = *(const ulonglong2*)(pC2a + rot);
                ulonglong2 wb = *(const ulonglong2*)(pC2a + 32 * 128 + rot);
                #pragma unroll
                for (int i = 0; i < 7; i++) {
                    ulonglong2 hp = ((const ulonglong2*)(h1W + i * 128))[d4];
                    fma2(bE0[i], hp.x, wa.x); fma2(bO0[i], hp.y, wa.y);
                    fma2(bE1[i], hp.x, wb.x); fma2(bO1[i], hp.y, wb.y);
                }
            }

            // residual (xn at dims l, l+32) + LN2, accumulate token sum
            float s2[7], ss2[7];
            float2 z[7];
            #pragma unroll
            for (int i = 0; i < 7; i++) {
                float2 f0 = up2(add2(bE0[i], bO0[i]));
                float2 f1 = up2(add2(bE1[i], bO1[i]));
                float v0 = fmaxf(f0.x + f0.y, 0.f);
                float v1 = fmaxf(f1.x + f1.y, 0.f);
                float z0 = xnW[i * 64 + lane]      + v0;
                float z1 = xnW[i * 64 + lane + 32] + v1;
                z[i] = make_float2(z0, z1);
                s2[i]  = z0 + z1;
                ss2[i] = z0 * z0 + z1 * z1;
            }
            #pragma unroll
            for (int o = 16; o > 0; o >>= 1) {
                #pragma unroll
                for (int i = 0; i < 7; i++) {
                    s2[i]  += __shfl_xor_sync(0xffffffffu, s2[i], o);
                    ss2[i] += __shfl_xor_sync(0xffffffffu, ss2[i], o);
                }
            }
            #pragma unroll
            for (int i = 0; i < 7; i++) {
                float mean = s2[i] * (1.f / 64.f);
                float var  = ss2[i] * (1.f / 64.f) - mean * mean;
                float rstd = rsqrtf(var + EPS_);
                xs.x += (z[i].x - mean) * rstd * g2a + b2a;
                xs.y += (z[i].y - mean) * rstd * g2b + b2b;
            }
        }
        __syncwarp();

        // decoder (folded) + fc; xs components are dims (l, l+32)
        xnW[lane]      = xs.x;
        xnW[lane + 32] = xs.y;
        __syncwarp();
        if (lane < NOUT_) {
            float o = sBf[lane];
            #pragma unroll 8
            for (int d = 0; d < 64; d++) o = fmaf(xnW[d], sWf[d * NOUT_ + lane], o);
            out[e * NOUT_ + lane] = o;
        }
        __syncwarp();
    }
}

extern "C" void kernel_launch(void* const* d_in, const int* in_sizes, int n_in,
                              void* d_out, int out_size) {
    const int*   tokens = (const int*)d_in[0];
    const float* emb    = (const float*)d_in[1];
    const float* pos    = (const float*)d_in[2];
    // d_in[3] qparam unused (decoder softmax over singleton q axis == 1)
    const float* in_w   = (const float*)d_in[4];
    const float* in_b   = (const float*)d_in[5];
    const float* e_wq   = (const float*)d_in[6];
    const float* e_wk   = (const float*)d_in[7];
    const float* e_wv   = (const float*)d_in[8];
    const float* e_wo   = (const float*)d_in[9];
    const float* e_bo   = (const float*)d_in[10];
    const float* e_g1   = (const float*)d_in[11];
    const float* e_b1   = (const float*)d_in[12];
    const float* e_c1w  = (const float*)d_in[13];
    const float* e_c1b  = (const float*)d_in[14];
    const float* e_c2w  = (const float*)d_in[15];
    const float* e_c2b  = (const float*)d_in[16];
    const float* e_g2   = (const float*)d_in[17];
    const float* e_b2   = (const float*)d_in[18];
    // d_in[19] d_wq, d_in[20] d_wk unused
    const float* d_wv   = (const float*)d_in[21];
    const float* d_wo   = (const float*)d_in[22];
    const float* d_bo   = (const float*)d_in[23];
    const float* fc_w   = (const float*)d_in[24];
    const float* fc_b   = (const float*)d_in[25];
    float* out = (float*)d_out;

    size_t prepSmem = 3 * 2688 * sizeof(float);
    k_prep<<<9, 1024, prepSmem>>>(emb, pos, in_w, in_b, e_wq, e_wk, e_wv, e_wo,
                                  d_wv, d_wo, d_bo, fc_w, fc_b, e_c1w, e_c2w);

    int dev = 0;
    cudaGetDevice(&dev);
    int smCount = 148;
    cudaDeviceGetAttribute(&smCount, cudaDevAttrMultiProcessorCount, dev);

    size_t smemBytes = SMEM_FLOATS * sizeof(float);
    cudaFuncSetAttribute(k_main, cudaFuncAttributeMaxDynamicSharedMemorySize, (int)smemBytes);
    k_main<<<smCount, NTHR, smemBytes>>>(tokens, e_bo, e_g1, e_b1, e_c1b, e_c2b,
                                         e_g2, e_b2, out, smCount * NWARP);
}

// round 11
// speedup vs baseline: 1.0547x; 1.0547x over previous
#include <cuda_runtime.h>

#define H_ 4
#define D_ 64
#define L_ 7
#define VOCAB_ 6
#define NOUT_ 11
#define BATCH_ 32768
#define EPS_ 1e-5f

using u64 = unsigned long long;

// ---- packed f32x2 helpers (sm_100+) ----
__device__ __forceinline__ u64 pk2(float x, float y) {
    u64 r; asm("mov.b64 %0, {%1, %2};" : "=l"(r) : "f"(x), "f"(y)); return r;
}
__device__ __forceinline__ u64 bc2(float x) {
    u64 r; asm("mov.b64 %0, {%1, %1};" : "=l"(r) : "f"(x)); return r;
}
__device__ __forceinline__ void fma2(u64& a, u64 x, u64 w) {
    asm("fma.rn.f32x2 %0, %1, %2, %0;" : "+l"(a) : "l"(x), "l"(w));
}
__device__ __forceinline__ float2 up2(u64 v) {
    float2 r; asm("mov.b64 {%0, %1}, %2;" : "=f"(r.x), "=f"(r.y) : "l"(v)); return r;
}

// ---------------- scratch (no allocations allowed) ----------------
__device__ float g_E[H_ * L_ * VOCAB_ * L_ * VOCAB_]; // [h][k][tk][q][tq]
__device__ float g_VW[H_ * L_ * VOCAB_ * D_];         // [(h*7+k)*6+tk][64]
__device__ float g_Wf[D_ * NOUT_];
__device__ float g_bf[NOUT_];
__device__ float g_C2p[64 * 128];   // [kk][c][2]: (C2[2kk][c], C2[2kk+1][c])

// ---------------- single merged prep kernel ----------------
__global__ void k_prep(const float* __restrict__ emb, const float* __restrict__ pos,
                       const float* __restrict__ in_w, const float* __restrict__ in_b,
                       const float* __restrict__ e_wq, const float* __restrict__ e_wk,
                       const float* __restrict__ e_wv, const float* __restrict__ e_wo,
                       const float* __restrict__ d_wv, const float* __restrict__ d_wo,
                       const float* __restrict__ d_bo,
                       const float* __restrict__ fc_w, const float* __restrict__ fc_b,
                       const float* __restrict__ c2w) {
    extern __shared__ float dyn[];
    int tid = threadIdx.x;
    int cta = blockIdx.x;

    if (cta < 8) {
        float* sT = dyn;          // 2688
        float* sA = dyn + 2688;   // 2688
        float* sB = dyn + 5376;   // 2688
        for (int i = tid; i < 42 * 64; i += 1024) {
            int lv = i >> 6, e = i & 63;
            int l = lv / 6, v = lv % 6;
            float acc = in_b[e];
            #pragma unroll 8
            for (int d = 0; d < 64; d++) acc = fmaf(emb[v * 64 + d], in_w[d * 64 + e], acc);
            acc = fmaf(pos[l], in_w[64 * 64 + e], acc);
            sT[i] = acc;
        }
        __syncthreads();
        int h = cta & 3;
        if (cta < 4) {
            for (int i = tid; i < 2 * 2688; i += 1024) {
                int which = i / 2688, r = i % 2688;
                int lv = r >> 6, e = r & 63;
                const float* w = which ? e_wk : e_wq;
                float acc = 0.f;
                #pragma unroll 8
                for (int d = 0; d < 64; d++) acc = fmaf(sT[lv * 64 + d], w[(h * 64 + d) * 64 + e], acc);
                (which ? sB : sA)[r] = acc;
            }
            __syncthreads();
            for (int i = tid; i < 1764; i += 1024) {
                int r = i;
                int tq = r % 6; r /= 6;
                int q  = r % 7; r /= 7;
                int tk = r % 6; r /= 6;
                int k  = r;
                const float* Q = sA + (q * 6 + tq) * 64;
                const float* K = sB + (k * 6 + tk) * 64;
                float s = 0.f;
                #pragma unroll 8
                for (int d = 0; d < 64; d++) s = fmaf(Q[d], K[d], s);
                g_E[h * 1764 + i] = __expf(s * 0.125f);
            }
        } else {
            for (int i = tid; i < 2688; i += 1024) {
                int lv = i >> 6, e = i & 63;
                float acc = 0.f;
                #pragma unroll 8
                for (int d = 0; d < 64; d++) acc = fmaf(sT[lv * 64 + d], e_wv[(h * 64 + d) * 64 + e], acc);
                sA[i] = acc;
            }
            __syncthreads();
            for (int i = tid; i < 2688; i += 1024) {
                int kv = i >> 6, e = i & 63;
                float acc = 0.f;
                #pragma unroll 8
                for (int d = 0; d < 64; d++) acc = fmaf(sA[kv * 64 + d], e_wo[(h * 64 + d) * 64 + e], acc);
                g_VW[(h * 42 + kv) * 64 + e] = acc;
            }
        }
    } else {
        float* sWd = dyn;  // 4096
        for (int i = tid; i < 4096; i += 1024) {
            int r = i >> 6, j = i & 63;
            float acc = 0.f;
            for (int hh = 0; hh < 4; hh++)
                #pragma unroll 8
                for (int d = 0; d < 64; d++)
                    acc = fmaf(d_wv[(hh * 64 + r) * 64 + d], d_wo[(hh * 64 + d) * 64 + j], acc);
            sWd[i] = acc;
        }
        __syncthreads();
        for (int i = tid; i < 64 * NOUT_; i += 1024) {
            int r = i / NOUT_, n = i % NOUT_;
            float acc = 0.f;
            #pragma unroll 8
            for (int j = 0; j < 64; j++) acc = fmaf(sWd[r * 64 + j], fc_w[j * NOUT_ + n], acc);
            g_Wf[i] = acc;
        }
        if (tid < NOUT_) {
            float b = fc_b[tid];
            #pragma unroll 8
            for (int j = 0; j < 64; j++) b = fmaf(d_bo[j], fc_w[j * NOUT_ + tid], b);
            g_bf[tid] = b;
        }
        // k-pair repacked FFN2 weights: g_C2p[kk*128 + c*2 + j] = c2w[(2kk+j)*64 + c]
        for (int i = tid; i < 64 * 128; i += 1024) {
            int kk = i >> 7, r = i & 127;
            int c = r >> 1, j = r & 1;
            g_C2p[i] = c2w[(2 * kk + j) * 64 + c];
        }
    }
}

// ---------------- main fused kernel ----------------
// 14 warps/CTA, 1 CTA/SM. SMEM (floats):
//   sE 7056 | sVW 10752 | sC1 8192 | sC2 8192 | sWf 704 | sBf 16   (=34912)
//   per-warp: wco 224 | xn 448 | h1 896  (=1568)
#define NWARP 14
#define NTHR  (NWARP * 32)
#define SMEM_FLOATS (34912 + NWARP * 1568)

__global__ __launch_bounds__(NTHR, 1)
void k_main(const int* __restrict__ tokens,
            const float* __restrict__ e_bo,
            const float* __restrict__ g1, const float* __restrict__ b1,
            const float* __restrict__ c1w, const float* __restrict__ c1b,
            const float* __restrict__ c2b,
            const float* __restrict__ g2, const float* __restrict__ b2,
            float* __restrict__ out, int totalWarps) {
    extern __shared__ float sm[];
    float* sE   = sm;                 // 7056
    float* sVW  = sE + 7056;          // 10752
    float* sC1  = sVW + 10752;        // 8192 (original [k][128])
    float* sC2  = sC1 + 8192;         // 8192 (k-pair repacked [kk][c][2])
    float* sWf  = sC2 + 8192;         // 704
    float* sBf  = sWf + 704;          // 16
    float* sWco = sBf + 16;           // NWARP*224
    float* sXn  = sWco + NWARP * 224; // NWARP*448
    float* sH1  = sXn + NWARP * 448;  // NWARP*896

    int tid = threadIdx.x;

    for (int i = tid; i < 7056 / 4;  i += NTHR) ((float4*)sE)[i]  = ((const float4*)g_E)[i];
    for (int i = tid; i < 10752 / 4; i += NTHR) ((float4*)sVW)[i] = ((const float4*)g_VW)[i];
    for (int i = tid; i < 8192 / 4;  i += NTHR) ((float4*)sC1)[i] = ((const float4*)c1w)[i];
    for (int i = tid; i < 8192 / 4;  i += NTHR) ((float4*)sC2)[i] = ((const float4*)g_C2p)[i];
    for (int i = tid; i < 704 / 4;   i += NTHR) ((float4*)sWf)[i] = ((const float4*)g_Wf)[i];
    if (tid < NOUT_) sBf[tid] = g_bf[tid];
    __syncthreads();

    int lane = tid & 31, wid = tid >> 5;

    float2 bo2  = ((const float2*)e_bo)[lane];
    float2 g1v  = ((const float2*)g1)[lane];
    float2 b1v  = ((const float2*)b1)[lane];
    float2 g2v  = ((const float2*)g2)[lane];
    float2 b2v  = ((const float2*)b2)[lane];
    float4 c1b4 = ((const float4*)c1b)[lane];
    float2 c2b2 = ((const float2*)c2b)[lane];
    u64 c1b01 = pk2(c1b4.x, c1b4.y), c1b23 = pk2(c1b4.z, c1b4.w);
    // FFN2 k-paired bias: bias in even slot, 0 in odd slot
    u64 c2bp0 = pk2(c2b2.x, 0.f), c2bp1 = pk2(c2b2.y, 0.f);

    float* wcoW = sWco + wid * 224;   // [j][8]
    float* xnW  = sXn + wid * 448;    // 7 rows of 64
    float* h1W  = sH1 + wid * 896;    // 7 rows of 128

    // FFN2 weight base for this lane (cols 2l, 2l+1): float offset kk*128 + 4*lane
    const float* pC2 = sC2 + 4 * lane;

    int gw = blockIdx.x * NWARP + wid;
    for (int e = gw; e < BATCH_; e += totalWarps) {
        // tokens: one coalesced LDG + shfl broadcast
        int myTok = 0;
        if (lane < 7) myTok = tokens[e * 7 + lane];
        int t[7];
        #pragma unroll
        for (int i = 0; i < 7; i++) t[i] = __shfl_sync(0xffffffffu, myTok, i);

        // softmax-over-q weights, packed wco[j][0..6]
        if (lane < 28) {
            int k = lane % 7;
            const float* eb = sE + (lane * 6 + t[k]) * 42;
            float myw[7];
            float den = 0.f;
            #pragma unroll
            for (int q = 0; q < 7; q++) { float x = eb[q * 6 + t[q]]; myw[q] = x; den += x; }
            float inv = __fdividef(1.f, den);
            float4 wA = make_float4(myw[0] * inv, myw[1] * inv, myw[2] * inv, myw[3] * inv);
            float4 wB = make_float4(myw[4] * inv, myw[5] * inv, myw[6] * inv, 0.f);
            ((float4*)(wcoW + lane * 8))[0] = wA;
            ((float4*)(wcoW + lane * 8))[1] = wB;
        }
        __syncwarp();

        // attention: y[q] = bo + sum_j w[q][j] * VW[j][t_k]
        float2 y[7];
        #pragma unroll
        for (int q = 0; q < 7; q++) y[q] = bo2;
        #pragma unroll
        for (int j = 0; j < 28; j++) {
            int k = j % 7;
            float2 v = ((const float2*)(sVW + (j * 6 + t[k]) * 64))[lane];
            float4 wA = ((const float4*)(wcoW + j * 8))[0];
            float4 wB = ((const float4*)(wcoW + j * 8))[1];
            y[0].x = fmaf(wA.x, v.x, y[0].x); y[0].y = fmaf(wA.x, v.y, y[0].y);
            y[1].x = fmaf(wA.y, v.x, y[1].x); y[1].y = fmaf(wA.y, v.y, y[1].y);
            y[2].x = fmaf(wA.z, v.x, y[2].x); y[2].y = fmaf(wA.z, v.y, y[2].y);
            y[3].x = fmaf(wA.w, v.x, y[3].x); y[3].y = fmaf(wA.w, v.y, y[3].y);
            y[4].x = fmaf(wB.x, v.x, y[4].x); y[4].y = fmaf(wB.x, v.y, y[4].y);
            y[5].x = fmaf(wB.y, v.x, y[5].x); y[5].y = fmaf(wB.y, v.y, y[5].y);
            y[6].x = fmaf(wB.z, v.x, y[6].x); y[6].y = fmaf(wB.z, v.y, y[6].y);
        }

        // LN1 for all 7 q at once (14 overlapping shfl chains), store xn to smem
        {
            float s1[7], ss1[7];
            #pragma unroll
            for (int q = 0; q < 7; q++) {
                s1[q]  = y[q].x + y[q].y;
                ss1[q] = y[q].x * y[q].x + y[q].y * y[q].y;
            }
            #pragma unroll
            for (int o = 16; o > 0; o >>= 1) {
                #pragma unroll
                for (int q = 0; q < 7; q++) {
                    s1[q]  += __shfl_xor_sync(0xffffffffu, s1[q], o);
                    ss1[q] += __shfl_xor_sync(0xffffffffu, ss1[q], o);
                }
            }
            #pragma unroll
            for (int q = 0; q < 7; q++) {
                float mean = s1[q] * (1.f / 64.f);
                float var  = ss1[q] * (1.f / 64.f) - mean * mean;
                float rstd = rsqrtf(var + EPS_);
                float2 xn;
                xn.x = (y[q].x - mean) * rstd * g1v.x + b1v.x;
                xn.y = (y[q].y - mean) * rstd * g1v.y + b1v.y;
                ((float2*)(xnW + q * 64))[lane] = xn;
            }
        }
        __syncwarp();

        // ---- FFN1: 64 -> 128, ALL 7 rows in one pass (weights read once) ----
        u64 a01[7], a23[7];
        #pragma unroll
        for (int i = 0; i < 7; i++) { a01[i] = c1b01; a23[i] = c1b23; }
        #pragma unroll 2
        for (int d4 = 0; d4 < 16; d4++) {
            const float4* wp = ((const float4*)sC1) + (d4 * 4) * 32 + lane;
            ulonglong2 w0 = *(const ulonglong2*)(wp);
            ulonglong2 w1 = *(const ulonglong2*)(wp + 32);
            ulonglong2 w2 = *(const ulonglong2*)(wp + 64);
            ulonglong2 w3 = *(const ulonglong2*)(wp + 96);
            #pragma unroll
            for (int i = 0; i < 7; i++) {
                float4 xv = ((const float4*)(xnW + i * 64))[d4];
                u64 xb;
                xb = bc2(xv.x); fma2(a01[i], xb, w0.x); fma2(a23[i], xb, w0.y);
                xb = bc2(xv.y); fma2(a01[i], xb, w1.x); fma2(a23[i], xb, w1.y);
                xb = bc2(xv.z); fma2(a01[i], xb, w2.x); fma2(a23[i], xb, w2.y);
                xb = bc2(xv.w); fma2(a01[i], xb, w3.x); fma2(a23[i], xb, w3.y);
            }
        }
        #pragma unroll
        for (int i = 0; i < 7; i++) {
            float2 p01 = up2(a01[i]), p23 = up2(a23[i]);
            float4 a;
            a.x = fmaxf(p01.x, 0.f); a.y = fmaxf(p01.y, 0.f);
            a.z = fmaxf(p23.x, 0.f); a.w = fmaxf(p23.y, 0.f);
            ((float4*)(h1W + i * 128))[lane] = a;
        }
        __syncwarp();

        // ---- FFN2: 128 -> 64, k-paired FMA2 with repacked weights ----
        // lane owns cols (2l, 2l+1); acc holds (even-k partial, odd-k partial)
        u64 ac0[7], ac1[7];
        #pragma unroll
        for (int i = 0; i < 7; i++) { ac0[i] = c2bp0; ac1[i] = c2bp1; }
        #pragma unroll 2
        for (int kk2 = 0; kk2 < 32; kk2++) {           // covers k = 4*kk2 .. 4*kk2+3
            ulonglong2 wa = *(const ulonglong2*)(pC2 + (2 * kk2) * 128);
            ulonglong2 wb = *(const ulonglong2*)(pC2 + (2 * kk2 + 1) * 128);
            #pragma unroll
            for (int i = 0; i < 7; i++) {
                ulonglong2 hp = ((const ulonglong2*)(h1W + i * 128))[kk2];
                fma2(ac0[i], hp.x, wa.x); fma2(ac1[i], hp.x, wa.y);
                fma2(ac0[i], hp.y, wb.x); fma2(ac1[i], hp.y, wb.y);
            }
        }

        // residual (xn reloaded from smem) + LN2, accumulate token sum
        float2 xs = make_float2(0.f, 0.f);
        {
            float s2[7], ss2[7];
            float2 z[7];
            #pragma unroll
            for (int i = 0; i < 7; i++) {
                float2 f0 = up2(ac0[i]);
                float2 f1 = up2(ac1[i]);
                float2 xn = ((const float2*)(xnW + i * 64))[lane];
                float zx = xn.x + fmaxf(f0.x + f0.y, 0.f);
                float zy = xn.y + fmaxf(f1.x + f1.y, 0.f);
                z[i] = make_float2(zx, zy);
                s2[i] = zx + zy;
                ss2[i] = zx * zx + zy * zy;
            }
            #pragma unroll
            for (int o = 16; o > 0; o >>= 1) {
                #pragma unroll
                for (int i = 0; i < 7; i++) {
                    s2[i]  += __shfl_xor_sync(0xffffffffu, s2[i], o);
                    ss2[i] += __shfl_xor_sync(0xffffffffu, ss2[i], o);
                }
            }
            #pragma unroll
            for (int i = 0; i < 7; i++) {
                float mean = s2[i] * (1.f / 64.f);
                float var  = ss2[i] * (1.f / 64.f) - mean * mean;
                float rstd = rsqrtf(var + EPS_);
                xs.x += (z[i].x - mean) * rstd * g2v.x + b2v.x;
                xs.y += (z[i].y - mean) * rstd * g2v.y + b2v.y;
            }
        }
        __syncwarp();

        // decoder (folded) + fc
        ((float2*)xnW)[lane] = xs;
        __syncwarp();
        if (lane < NOUT_) {
            float o = sBf[lane];
            #pragma unroll 8
            for (int d = 0; d < 64; d++) o = fmaf(xnW[d], sWf[d * NOUT_ + lane], o);
            out[e * NOUT_ + lane] = o;
        }
        __syncwarp();
    }
}

extern "C" void kernel_launch(void* const* d_in, const int* in_sizes, int n_in,
                              void* d_out, int out_size) {
    const int*   tokens = (const int*)d_in[0];
    const float* emb    = (const float*)d_in[1];
    const float* pos    = (const float*)d_in[2];
    // d_in[3] qparam unused (decoder softmax over singleton q axis == 1)
    const float* in_w   = (const float*)d_in[4];
    const float* in_b   = (const float*)d_in[5];
    const float* e_wq   = (const float*)d_in[6];
    const float* e_wk   = (const float*)d_in[7];
    const float* e_wv   = (const float*)d_in[8];
    const float* e_wo   = (const float*)d_in[9];
    const float* e_bo   = (const float*)d_in[10];
    const float* e_g1   = (const float*)d_in[11];
    const float* e_b1   = (const float*)d_in[12];
    const float* e_c1w  = (const float*)d_in[13];
    const float* e_c1b  = (const float*)d_in[14];
    const float* e_c2w  = (const float*)d_in[15];
    const float* e_c2b  = (const float*)d_in[16];
    const float* e_g2   = (const float*)d_in[17];
    const float* e_b2   = (const float*)d_in[18];
    // d_in[19] d_wq, d_in[20] d_wk unused
    const float* d_wv   = (const float*)d_in[21];
    const float* d_wo   = (const float*)d_in[22];
    const float* d_bo   = (const float*)d_in[23];
    const float* fc_w   = (const float*)d_in[24];
    const float* fc_b   = (const float*)d_in[25];
    float* out = (float*)d_out;

    size_t prepSmem = 3 * 2688 * sizeof(float);
    k_prep<<<9, 1024, prepSmem>>>(emb, pos, in_w, in_b, e_wq, e_wk, e_wv, e_wo,
                                  d_wv, d_wo, d_bo, fc_w, fc_b, e_c2w);

    int dev = 0;
    cudaGetDevice(&dev);
    int smCount = 148;
    cudaDeviceGetAttribute(&smCount, cudaDevAttrMultiProcessorCount, dev);

    size_t smemBytes = SMEM_FLOATS * sizeof(float);
    cudaFuncSetAttribute(k_main, cudaFuncAttributeMaxDynamicSharedMemorySize, (int)smemBytes);
    k_main<<<smCount, NTHR, smemBytes>>>(tokens, e_bo, e_g1, e_b1, e_c1w, e_c1b,
                                         e_c2b, e_g2, e_b2, out, smCount * NWARP);
}